// round 1
// baseline (speedup 1.0000x reference)
#include <cuda_runtime.h>
#include <cstdint>

#define F    128
#define NI   31
#define NL   32
#define MAXT 32

typedef unsigned long long u64;

// Scratch (allocation-free: __device__ globals)
__device__ float g_Wm[MAXT * NI * F];   // masked split weights
__device__ float g_sc[MAXT * NL * 2];   // softmax(tree_w)[t] * softmax(leaf_logits)[t,l,:]

// ---------------- prologue kernels ----------------

__global__ void prep_wm(const float* __restrict__ sw, const float* __restrict__ fm, int T) {
    int idx = blockIdx.x * blockDim.x + threadIdx.x;
    int total = T * NI * F;
    if (idx >= total) return;
    int t = idx / (NI * F);
    int f = idx % F;
    g_Wm[idx] = sw[idx] * fm[t * F + f];
}

__global__ void prep_sc(const float* __restrict__ leaf_logits, const float* __restrict__ tw, int T) {
    int i = blockIdx.x * blockDim.x + threadIdx.x;
    if (i >= T * NL) return;
    int t = i / NL;
    // softmax over tree weights (T small; redundant per-thread is fine)
    float m = -1e30f;
    for (int k = 0; k < T; k++) m = fmaxf(m, tw[k]);
    float den = 0.f;
    for (int k = 0; k < T; k++) den += expf(tw[k] - m);
    float w = expf(tw[t] - m) / den;
    // softmax over 2 classes
    float a = leaf_logits[i * 2 + 0];
    float b = leaf_logits[i * 2 + 1];
    float mm = fmaxf(a, b);
    float ea = expf(a - mm), eb = expf(b - mm);
    float inv = 1.f / (ea + eb);
    g_sc[i * 2 + 0] = w * ea * inv;
    g_sc[i * 2 + 1] = w * eb * inv;
}

// ---------------- main fused kernel ----------------
// One thread per row. x row lives in registers as 64 packed f32x2.
// Per tree: masked weights staged in SMEM; 31 dot products via fma.rn.f32x2
// (weights loaded as LDS.64 broadcast straight into the packed FMA — no repack);
// sigmoid via ex2.approx + rcp.approx; sigmoids parked in SMEM (own column,
// conflict-free) so the node loop stays rolled; path-product epilogue fully
// unrolled with compile-time heap indices.

__global__ void __launch_bounds__(128) forest_main(
    const float* __restrict__ x, const float* __restrict__ bias,
    float* __restrict__ out, int B, int T)
{
    __shared__ alignas(16) float wsh[NI * F];     // 15872 B
    __shared__ float s_sh[NI][128];               // 15872 B (per-thread column)
    __shared__ float scsh[NL * 2];
    __shared__ float bsh[NI];

    const int tid = threadIdx.x;
    const int row = blockIdx.x * 128 + tid;
    const bool active = row < B;

    u64 xp[F / 2];
    if (active) {
        const ulonglong2* xg = (const ulonglong2*)(x + (size_t)row * F);
        #pragma unroll
        for (int i = 0; i < F / 4; i++) {
            ulonglong2 v = xg[i];
            xp[2 * i]     = v.x;
            xp[2 * i + 1] = v.y;
        }
    } else {
        #pragma unroll
        for (int i = 0; i < F / 2; i++) xp[i] = 0ull;
    }

    float o0 = 0.f, o1 = 0.f;

    for (int t = 0; t < T; t++) {
        __syncthreads();   // protect wsh/scsh against previous-tree readers
        {
            const float4* wg  = (const float4*)(g_Wm + (size_t)t * NI * F);
            float4*       ws4 = (float4*)wsh;
            #pragma unroll 2
            for (int i = tid; i < NI * F / 4; i += 128) ws4[i] = wg[i];
            if (tid < NL * 2) scsh[tid] = g_sc[t * NL * 2 + tid];
            if (tid < NI)     bsh[tid]  = bias[t * NI + tid];
        }
        __syncthreads();

        // --- 31 dot products (f32x2 packed FMA, 4 independent accumulators) ---
        for (int n = 0; n < NI; n++) {
            const u64* w2 = (const u64*)(wsh + n * F);
            u64 a0 = 0ull, a1 = 0ull, a2 = 0ull, a3 = 0ull;
            #pragma unroll
            for (int i = 0; i < 16; i++) {
                asm("fma.rn.f32x2 %0, %1, %2, %0;" : "+l"(a0) : "l"(xp[4 * i + 0]), "l"(w2[4 * i + 0]));
                asm("fma.rn.f32x2 %0, %1, %2, %0;" : "+l"(a1) : "l"(xp[4 * i + 1]), "l"(w2[4 * i + 1]));
                asm("fma.rn.f32x2 %0, %1, %2, %0;" : "+l"(a2) : "l"(xp[4 * i + 2]), "l"(w2[4 * i + 2]));
                asm("fma.rn.f32x2 %0, %1, %2, %0;" : "+l"(a3) : "l"(xp[4 * i + 3]), "l"(w2[4 * i + 3]));
            }
            asm("add.rn.f32x2 %0, %0, %1;" : "+l"(a0) : "l"(a2));
            asm("add.rn.f32x2 %0, %0, %1;" : "+l"(a1) : "l"(a3));
            asm("add.rn.f32x2 %0, %0, %1;" : "+l"(a0) : "l"(a1));
            float lo, hi;
            asm("mov.b64 {%0,%1}, %2;" : "=f"(lo), "=f"(hi) : "l"(a0));
            float logit = lo + hi + bsh[n];
            // sigmoid(x) = 1 / (1 + 2^(-x*log2(e)))
            float e, sg;
            asm("ex2.approx.f32 %0, %1;" : "=f"(e) : "f"(logit * -1.4426950408889634f));
            asm("rcp.approx.f32 %0, %1;" : "=f"(sg) : "f"(1.0f + e));
            s_sh[n][tid] = sg;   // own column: no cross-thread dep, no sync needed
        }

        // --- path-product epilogue (heap order: children of i are 2i+1 (left), 2i+2 (right)) ---
        float Pn[NI];
        Pn[0] = 1.f;
        #pragma unroll
        for (int i = 0; i < 15; i++) {
            float g = s_sh[i][tid];
            Pn[2 * i + 1] = Pn[i] * (1.f - g);   // odd node  = left  -> (1-g)
            Pn[2 * i + 2] = Pn[i] * g;           // even node = right -> g
        }
        #pragma unroll
        for (int l = 0; l < NL; l++) {
            const int p = (30 + l) >> 1;         // parent of leaf node 31+l
            float g  = s_sh[p][tid];
            float pl = Pn[p] * ((l & 1) ? g : (1.f - g));  // node 31+l even <=> l odd <=> right
            o0 += pl * scsh[2 * l + 0];
            o1 += pl * scsh[2 * l + 1];
        }
    }

    if (active) {
        out[(size_t)row * 2 + 0] = o0;
        out[(size_t)row * 2 + 1] = o1;
    }
}

// ---------------- launch ----------------

extern "C" void kernel_launch(void* const* d_in, const int* in_sizes, int n_in,
                              void* d_out, int out_size)
{
    const float* x  = (const float*)d_in[0];  // [B, 128]
    const float* sw = (const float*)d_in[1];  // [T, 31, 128]
    const float* sb = (const float*)d_in[2];  // [T, 31]
    const float* ll = (const float*)d_in[3];  // [T, 32, 2]
    const float* tw = (const float*)d_in[4];  // [T]
    const float* fm = (const float*)d_in[5];  // [T, 128]

    int T = in_sizes[4];
    if (T > MAXT) T = MAXT;
    int B = in_sizes[0] / F;

    int tot = T * NI * F;
    prep_wm<<<(tot + 255) / 256, 256>>>(sw, fm, T);
    prep_sc<<<(T * NL + 127) / 128, 128>>>(ll, tw, T);
    forest_main<<<(B + 127) / 128, 128>>>(x, sb, (float*)d_out, B, T);
}

// round 4
// speedup vs baseline: 3.7992x; 3.7992x over previous
#include <cuda_runtime.h>
#include <cstdint>

typedef unsigned int u32;
typedef unsigned long long u64;

#define F       128
#define NI      31
#define NL      32
#define TMAX    20
#define NGROUP  5            // 5 groups x 4 trees (cols 128 per group)
#define TILE_M  128
#define NTHREADS 256

// ---- SMEM layout (float indices) ----
#define STW    132           // W/X row stride (floats): banks (4n+k)%32 conflict-free
#define STL    129           // logits row stride: banks (r+c)%32 conflict-free
#define X_F    0                         // 128*132 = 16896
#define W0_F   16896                     // 16896
#define W1_F   33792                     // 16896
#define BS_F   50688                     // 620 -> pad 624
#define SC_F   51312                     // 1280
#define SP_F   52592                     // 512
#define SMEM_FLOATS 53104
#define SMEM_BYTES  (SMEM_FLOATS * 4)    // 212416

// __device__ scratch (allocation-free)
__device__ float g_W[NGROUP * 128 * F];  // tf32-rounded masked weights [g][nrow=tl*32+n][k]
__device__ float g_sc[TMAX * NL * 2];    // softmax(tree_w)[t] * softmax(leaf_logits)[t,l,:]

// ---------------- helpers ----------------
__device__ __forceinline__ u32 smem_u32(const void* p) {
    u32 a;
    asm("{ .reg .u64 t; cvta.to.shared.u64 t, %1; cvt.u32.u64 %0, t; }" : "=r"(a) : "l"(p));
    return a;
}
__device__ __forceinline__ void cpa16(u32 dst, const void* src) {
    asm volatile("cp.async.cg.shared.global [%0], [%1], 16;" :: "r"(dst), "l"(src) : "memory");
}
#define CP_COMMIT() asm volatile("cp.async.commit_group;" ::: "memory")
template<int N> __device__ __forceinline__ void cp_wait() {
    asm volatile("cp.async.wait_group %0;" :: "n"(N) : "memory");
}

#define MMA_TF32(c, a, b0, b1) \
    asm volatile("mma.sync.aligned.m16n8k8.row.col.f32.tf32.tf32.f32 " \
        "{%0,%1,%2,%3}, {%4,%5,%6,%7}, {%8,%9}, {%0,%1,%2,%3};" \
        : "+f"((c)[0]), "+f"((c)[1]), "+f"((c)[2]), "+f"((c)[3]) \
        : "r"((a)[0]), "r"((a)[1]), "r"((a)[2]), "r"((a)[3]), "r"(b0), "r"(b1))

// ---------------- prologue ----------------
__global__ void prep(const float* __restrict__ sw, const float* __restrict__ fm,
                     const float* __restrict__ ll, const float* __restrict__ tw, int T) {
    int idx = blockIdx.x * 256 + threadIdx.x;
    const int total = NGROUP * 128 * F;   // 81920
    if (idx < total) {
        int k    = idx & 127;
        int nrow = (idx >> 7) & 127;
        int g    = idx >> 14;
        int t    = g * 4 + (nrow >> 5);
        int n    = nrow & 31;
        float v = 0.f;
        if (t < T && n < NI) v = sw[(t * NI + n) * F + k] * fm[t * F + k];
        u32 o;
        asm("cvt.rna.tf32.f32 %0, %1;" : "=r"(o) : "f"(v));
        ((u32*)g_W)[idx] = o;
    }
    if (idx < TMAX * NL) {
        int t = idx >> 5, l = idx & 31;
        float w0 = 0.f, w1 = 0.f;
        if (t < T) {
            float m = -1e30f;
            for (int k = 0; k < T; k++) m = fmaxf(m, tw[k]);
            float den = 0.f;
            for (int k = 0; k < T; k++) den += expf(tw[k] - m);
            float w = expf(tw[t] - m) / den;
            float a = ll[(t * NL + l) * 2 + 0];
            float b = ll[(t * NL + l) * 2 + 1];
            float mm = fmaxf(a, b);
            float ea = expf(a - mm), eb = expf(b - mm);
            float inv = w / (ea + eb);
            w0 = ea * inv; w1 = eb * inv;
        }
        g_sc[idx * 2 + 0] = w0;
        g_sc[idx * 2 + 1] = w1;
    }
}

// ---------------- main fused kernel ----------------
// 256 threads. GEMM: 8 warps as 4(M)x2(N); mma.sync m16n8k8 tf32.
// X resident in SMEM; W double-buffered via cp.async; logits staged into the
// just-consumed W buffer (stride 129). Epilogue: sigmoid + path product.
__global__ void __launch_bounds__(NTHREADS, 1) forest_mma(
    const float* __restrict__ x, const float* __restrict__ sb,
    float* __restrict__ out, int B, int T)
{
    extern __shared__ char smem[];
    float* smf = (float*)smem;
    const u32 sbase = smem_u32(smem);
    const int tid  = threadIdx.x;
    const int wid  = tid >> 5;
    const int lane = tid & 31;
    const int gid  = lane >> 2;      // group of 4 lanes
    const int tid4 = lane & 3;
    const int warp_m = wid & 3;      // 4 M-groups of 32 rows
    const int warp_n = wid >> 2;     // 2 N-groups of 64 cols
    const int m0 = blockIdx.x * TILE_M;

    // ---- stage X tile + W group 0 (one commit group) ----
    for (int i = tid; i < 4096; i += NTHREADS) {
        int row = i >> 5, c = i & 31;
        int srow = m0 + row; if (srow >= B) srow = B - 1;
        cpa16(sbase + (u32)(X_F + row * STW) * 4 + c * 16, x + (size_t)srow * F + c * 4);
    }
    for (int i = tid; i < 4096; i += NTHREADS) {
        int row = i >> 5, c = i & 31;
        cpa16(sbase + (u32)(W0_F + row * STW) * 4 + c * 16, g_W + row * F + c * 4);
    }
    CP_COMMIT();

    // ---- stage bias + leaf/class scales (regular stores) ----
    for (int i = tid; i < TMAX * NI; i += NTHREADS)
        smf[BS_F + i] = (i < T * NI) ? sb[i] : 0.f;
    for (int i = tid; i < TMAX * 64; i += NTHREADS)
        smf[SC_F + i] = g_sc[i];

    float o0 = 0.f, o1 = 0.f;
    const int erow = tid & 127;      // epilogue row
    const int ej   = tid >> 7;       // 0/1 -> tree pair within group

    #pragma unroll 1
    for (int g = 0; g < NGROUP; g++) {
        const int wf  = (g & 1) ? W1_F : W0_F;   // current W / logits buffer
        const int wfn = (g & 1) ? W0_F : W1_F;   // next W buffer

        __syncthreads();   // epilogue g-1 reads of buffer wfn complete
        if (g < NGROUP - 1) {
            const float* src = g_W + (size_t)(g + 1) * 128 * F;
            for (int i = tid; i < 4096; i += NTHREADS) {
                int row = i >> 5, c = i & 31;
                cpa16(sbase + (u32)(wfn + row * STW) * 4 + c * 16, src + row * F + c * 4);
            }
            CP_COMMIT();
            cp_wait<1>();
        } else {
            cp_wait<0>();
        }
        __syncthreads();   // W[g] visible to all warps

        // ================= GEMM chunk g =================
        float acc[2][8][4];
        #pragma unroll
        for (int mt = 0; mt < 2; mt++)
            #pragma unroll
            for (int nt = 0; nt < 8; nt++)
                #pragma unroll
                for (int q = 0; q < 4; q++) acc[mt][nt][q] = 0.f;

        const u32* Xa = (const u32*)smf + X_F + (warp_m * 32 + gid) * STW + tid4;
        const u32* Wb = (const u32*)smf + wf  + (warp_n * 64 + gid) * STW + tid4;

        #pragma unroll
        for (int kk = 0; kk < 16; kk++) {
            const int ko = kk * 8;
            u32 a[2][4];
            #pragma unroll
            for (int mt = 0; mt < 2; mt++) {
                a[mt][0] = Xa[(mt * 16    ) * STW + ko    ];
                a[mt][1] = Xa[(mt * 16 + 8) * STW + ko    ];
                a[mt][2] = Xa[(mt * 16    ) * STW + ko + 4];
                a[mt][3] = Xa[(mt * 16 + 8) * STW + ko + 4];
            }
            #pragma unroll
            for (int nt = 0; nt < 8; nt++) {
                u32 b0 = Wb[(nt * 8) * STW + ko    ];
                u32 b1 = Wb[(nt * 8) * STW + ko + 4];
                MMA_TF32(acc[0][nt], a[0], b0, b1);
                MMA_TF32(acc[1][nt], a[1], b0, b1);
            }
        }

        __syncthreads();   // all W reads done; buffer wf reusable for logits

        // stage logits (stride 129, conflict-free epilogue reads)
        {
            float* Ls = smf + wf;
            #pragma unroll
            for (int mt = 0; mt < 2; mt++)
                #pragma unroll
                for (int nt = 0; nt < 8; nt++) {
                    int r = warp_m * 32 + mt * 16 + gid;
                    int c = warp_n * 64 + nt * 8 + tid4 * 2;
                    Ls[ r      * STL + c    ] = acc[mt][nt][0];
                    Ls[ r      * STL + c + 1] = acc[mt][nt][1];
                    Ls[(r + 8) * STL + c    ] = acc[mt][nt][2];
                    Ls[(r + 8) * STL + c + 1] = acc[mt][nt][3];
                }
        }
        __syncthreads();   // logits visible

        // ================= epilogue chunk g =================
        const float* Lr = smf + wf + erow * STL;
        #pragma unroll
        for (int jt = 0; jt < 2; jt++) {
            const int tl = ej * 2 + jt;
            const int t  = g * 4 + tl;
            const float* bs = smf + BS_F + t * NI;
            const float* sc = smf + SC_F + t * 64;
            float s[NI];
            #pragma unroll
            for (int n = 0; n < NI; n++) {
                float lg = Lr[tl * 32 + n] + bs[n];
                float e, sg;
                asm("ex2.approx.f32 %0, %1;" : "=f"(e) : "f"(lg * -1.4426950408889634f));
                asm("rcp.approx.f32 %0, %1;" : "=f"(sg) : "f"(1.0f + e));
                s[n] = sg;
            }
            float Pn[NI];
            Pn[0] = 1.f;
            #pragma unroll
            for (int i = 0; i < 15; i++) {
                float gg = s[i];
                Pn[2 * i + 1] = Pn[i] * (1.f - gg);
                Pn[2 * i + 2] = Pn[i] * gg;
            }
            #pragma unroll
            for (int l = 0; l < NL; l++) {
                const int p = (30 + l) >> 1;
                float gg = s[p];
                float pl = Pn[p] * ((l & 1) ? gg : (1.f - gg));
                o0 += pl * sc[2 * l + 0];
                o1 += pl * sc[2 * l + 1];
            }
        }
    }

    // ---- combine the two partial-sum threads per row, write out ----
    smf[SP_F + tid * 2 + 0] = o0;
    smf[SP_F + tid * 2 + 1] = o1;
    __syncthreads();
    if (tid < 128) {
        float a0 = smf[SP_F + tid * 2 + 0] + smf[SP_F + (tid + 128) * 2 + 0];
        float a1 = smf[SP_F + tid * 2 + 1] + smf[SP_F + (tid + 128) * 2 + 1];
        int row = m0 + tid;
        if (row < B) ((float2*)out)[row] = make_float2(a0, a1);
    }
}

// ---------------- launch ----------------
extern "C" void kernel_launch(void* const* d_in, const int* in_sizes, int n_in,
                              void* d_out, int out_size)
{
    const float* x  = (const float*)d_in[0];  // [B, 128]
    const float* sw = (const float*)d_in[1];  // [T, 31, 128]
    const float* sb = (const float*)d_in[2];  // [T, 31]
    const float* ll = (const float*)d_in[3];  // [T, 32, 2]
    const float* tw = (const float*)d_in[4];  // [T]
    const float* fm = (const float*)d_in[5];  // [T, 128]

    int T = in_sizes[4];
    if (T > TMAX) T = TMAX;
    int B = in_sizes[0] / F;

    cudaFuncSetAttribute(forest_mma, cudaFuncAttributeMaxDynamicSharedMemorySize, SMEM_BYTES);

    prep<<<(NGROUP * 128 * F + 255) / 256, 256>>>(sw, fm, ll, tw, T);
    forest_mma<<<(B + TILE_M - 1) / TILE_M, NTHREADS, SMEM_BYTES>>>(x, sb, (float*)d_out, B, T);
}